// round 1
// baseline (speedup 1.0000x reference)
#include <cuda_runtime.h>
#include <math.h>

// Problem constants
#define B2      2
#define SEQ     2048
#define DM      2048
#define NH      16
#define NKV     4
#define HD      128
#define BS_TOTAL (B2*SEQ)        // 4096
#define KVW     (NKV*HD)         // 512

// ---------------- scratch (allocation-free: __device__ globals) ----------------
__device__ float g_Q[(size_t)BS_TOTAL * DM];    // 32 MB
__device__ float g_K[(size_t)BS_TOTAL * KVW];   // 8 MB
__device__ float g_V[(size_t)BS_TOTAL * KVW];   // 8 MB
__device__ float g_O[(size_t)BS_TOTAL * DM];    // 32 MB
__device__ float g_cos[SEQ * 64];
__device__ float g_sin[SEQ * 64];

// ---------------- RoPE table (fp64 phase -> fp32 cos/sin) ----------------
__global__ void rope_table_kernel() {
    int idx = blockIdx.x * blockDim.x + threadIdx.x;
    if (idx >= SEQ * 64) return;
    int s = idx >> 6, j = idx & 63;
    double inv = 1.0 / pow(10000.0, (double)(2 * j) / 128.0);
    double ph = (double)s * inv;
    g_cos[idx] = (float)cos(ph);
    g_sin[idx] = (float)sin(ph);
}

// ---------------- RoPE apply (in-place, NeoX pairing d <-> d+64) ----------------
__global__ void rope_apply_kernel(float* __restrict__ buf, int nheads) {
    int idx = blockIdx.x * blockDim.x + threadIdx.x;
    int total = BS_TOTAL * nheads * 64;
    if (idx >= total) return;
    int j = idx & 63;
    int tmp = idx >> 6;
    int h = tmp % nheads;
    int rowi = tmp / nheads;
    int s = rowi & (SEQ - 1);
    float c = g_cos[s * 64 + j];
    float sn = g_sin[s * 64 + j];
    size_t base = (size_t)rowi * (nheads * HD) + h * HD + j;
    float x1 = buf[base];
    float x2 = buf[base + 64];
    buf[base]      = x1 * c - x2 * sn;
    buf[base + 64] = x2 * c + x1 * sn;
}

// ---------------- NT SGEMM: C[M,N] = A[M,K] * B[N,K]^T (fp32) ----------------
// 128x128 tile, 256 threads, 8x8 microtile, BK=16, register prefetch.
__global__ __launch_bounds__(256) void sgemm_nt(
    const float* __restrict__ A, const float* __restrict__ B,
    float* __restrict__ C, int M, int N, int K)
{
    __shared__ float As[16][132];
    __shared__ float Bs[16][132];
    const int t  = threadIdx.x;
    const int m0 = blockIdx.y * 128;
    const int n0 = blockIdx.x * 128;
    const int tx = t & 15, ty = t >> 4;   // 16x16 threads; ty->m, tx->n
    const int row = t >> 2, kq = t & 3;   // load roles

    const float* Ag = A + (size_t)(m0 + row) * K + kq * 4;
    const float* Bg = B + (size_t)(n0 + row) * K + kq * 4;

    float acc[8][8];
    #pragma unroll
    for (int i = 0; i < 8; i++)
        #pragma unroll
        for (int j = 0; j < 8; j++) acc[i][j] = 0.f;

    float4 a0, a1, b0, b1;
    a0 = *(const float4*)(Ag);
    a1 = *(const float4*)(Ag + (size_t)64 * K);
    b0 = *(const float4*)(Bg);
    b1 = *(const float4*)(Bg + (size_t)64 * K);

    auto store_sm = [&]() {
        #pragma unroll
        for (int c = 0; c < 4; c++) {
            As[kq * 4 + c][row]      = ((const float*)&a0)[c];
            As[kq * 4 + c][row + 64] = ((const float*)&a1)[c];
            Bs[kq * 4 + c][row]      = ((const float*)&b0)[c];
            Bs[kq * 4 + c][row + 64] = ((const float*)&b1)[c];
        }
    };
    store_sm();
    __syncthreads();

    for (int kb = 0; kb < K; kb += 16) {
        const bool has_next = (kb + 16) < K;
        if (has_next) {
            a0 = *(const float4*)(Ag + kb + 16);
            a1 = *(const float4*)(Ag + (size_t)64 * K + kb + 16);
            b0 = *(const float4*)(Bg + kb + 16);
            b1 = *(const float4*)(Bg + (size_t)64 * K + kb + 16);
        }
        #pragma unroll
        for (int kk = 0; kk < 16; kk++) {
            float af[8], bf[8];
            *(float4*)&af[0] = *(const float4*)&As[kk][ty * 8];
            *(float4*)&af[4] = *(const float4*)&As[kk][ty * 8 + 4];
            *(float4*)&bf[0] = *(const float4*)&Bs[kk][tx * 8];
            *(float4*)&bf[4] = *(const float4*)&Bs[kk][tx * 8 + 4];
            #pragma unroll
            for (int i = 0; i < 8; i++)
                #pragma unroll
                for (int j = 0; j < 8; j++)
                    acc[i][j] += af[i] * bf[j];
        }
        if (has_next) {
            __syncthreads();
            store_sm();
            __syncthreads();
        }
    }

    #pragma unroll
    for (int i = 0; i < 8; i++) {
        float* Cp = C + (size_t)(m0 + ty * 8 + i) * N + n0 + tx * 8;
        #pragma unroll
        for (int j = 0; j < 8; j += 4) {
            float4 v = make_float4(acc[i][j], acc[i][j+1], acc[i][j+2], acc[i][j+3]);
            *(float4*)(Cp + j) = v;
        }
    }
}

// ---------------- Flash attention (causal, GQA), fp32 ----------------
// Block: 128 threads. Tile: 32 queries x 32 keys. Each row owned by 4 threads
// (d split into 4x32). Q in registers; K/V in shared with 36-float quarter
// stride (kills 128B-periodic bank conflicts). Score dot reduced via shfl_xor.
__global__ __launch_bounds__(128) void attn_kernel() {
    __shared__ float k_s[32][144];
    __shared__ float v_s[32][144];
    const int qt = blockIdx.x, h = blockIdx.y, b = blockIdx.z;
    const int t = threadIdx.x;
    const int i = t >> 2, quarter = t & 3;
    const int q0 = qt * 32;
    const int kvh = h >> 2;
    const int sq = q0 + i;
    const size_t qrow = (size_t)(b * SEQ + sq);
    const float scale = 0.08838834764831845f;  // 1/sqrt(128)

    float q[32];
    {
        const float* qp = g_Q + qrow * DM + h * HD + quarter * 32;
        #pragma unroll
        for (int c = 0; c < 8; c++) {
            float4 v = *(const float4*)(qp + c * 4);
            q[c*4+0] = v.x * scale; q[c*4+1] = v.y * scale;
            q[c*4+2] = v.z * scale; q[c*4+3] = v.w * scale;
        }
    }
    float o[32];
    #pragma unroll
    for (int dd = 0; dd < 32; dd++) o[dd] = 0.f;
    float m = -INFINITY, l = 0.f;

    const int jrow = t >> 2, qq = t & 3;  // K/V load roles
    const int ntiles = qt + 1;            // causal: only tiles with k0 <= q0

    for (int kt = 0; kt < ntiles; kt++) {
        const int k0 = kt * 32;
        __syncthreads();
        {
            const float* kp = g_K + (size_t)(b * SEQ + k0 + jrow) * KVW + kvh * HD + qq * 32;
            const float* vp = g_V + (size_t)(b * SEQ + k0 + jrow) * KVW + kvh * HD + qq * 32;
            #pragma unroll
            for (int c = 0; c < 8; c++) {
                float4 kv = *(const float4*)(kp + c * 4);
                float4 vv = *(const float4*)(vp + c * 4);
                *(float4*)&k_s[jrow][qq * 36 + c * 4] = kv;
                *(float4*)&v_s[jrow][qq * 36 + c * 4] = vv;
            }
        }
        __syncthreads();

        float s[32];
        #pragma unroll
        for (int j = 0; j < 32; j++) {
            const float* kr = &k_s[j][quarter * 36];
            float acc = 0.f;
            #pragma unroll
            for (int dd = 0; dd < 32; dd += 4) {
                float4 kv = *(const float4*)(kr + dd);
                acc += q[dd] * kv.x + q[dd+1] * kv.y + q[dd+2] * kv.z + q[dd+3] * kv.w;
            }
            acc += __shfl_xor_sync(0xffffffffu, acc, 1);
            acc += __shfl_xor_sync(0xffffffffu, acc, 2);
            s[j] = acc;
        }
        if (kt == qt) {  // diagonal tile: causal mask
            #pragma unroll
            for (int j = 0; j < 32; j++)
                if (k0 + j > sq) s[j] = -INFINITY;
        }

        float mt = s[0];
        #pragma unroll
        for (int j = 1; j < 32; j++) mt = fmaxf(mt, s[j]);
        float mn = fmaxf(m, mt);
        float corr = __expf(fmaxf(m - mn, -80.f));  // safe at m = -inf
        l *= corr;
        #pragma unroll
        for (int dd = 0; dd < 32; dd++) o[dd] *= corr;
        float ls = 0.f;
        #pragma unroll
        for (int j = 0; j < 32; j++) {
            float p = __expf(s[j] - mn);
            s[j] = p;
            ls += p;
        }
        l += ls;
        m = mn;

        #pragma unroll
        for (int j = 0; j < 32; j++) {
            const float pj = s[j];
            const float* vr = &v_s[j][quarter * 36];
            #pragma unroll
            for (int dd = 0; dd < 32; dd += 4) {
                float4 vv = *(const float4*)(vr + dd);
                o[dd]   += pj * vv.x; o[dd+1] += pj * vv.y;
                o[dd+2] += pj * vv.z; o[dd+3] += pj * vv.w;
            }
        }
    }

    const float invl = 1.f / l;
    float* op = g_O + qrow * DM + h * HD + quarter * 32;
    #pragma unroll
    for (int c = 0; c < 8; c++) {
        float4 v = make_float4(o[c*4]*invl, o[c*4+1]*invl, o[c*4+2]*invl, o[c*4+3]*invl);
        *(float4*)(op + c * 4) = v;
    }
}

// ---------------- launch ----------------
extern "C" void kernel_launch(void* const* d_in, const int* in_sizes, int n_in,
                              void* d_out, int out_size) {
    const float* x  = (const float*)d_in[0];
    const float* wq = (const float*)d_in[1];
    const float* wk = (const float*)d_in[2];
    const float* wv = (const float*)d_in[3];
    const float* wo = (const float*)d_in[4];
    float* out = (float*)d_out;

    float *pQ, *pK, *pV, *pO;
    cudaGetSymbolAddress((void**)&pQ, g_Q);
    cudaGetSymbolAddress((void**)&pK, g_K);
    cudaGetSymbolAddress((void**)&pV, g_V);
    cudaGetSymbolAddress((void**)&pO, g_O);

    rope_table_kernel<<<(SEQ * 64 + 255) / 256, 256>>>();

    // QKV projections: C = X @ W^T
    sgemm_nt<<<dim3(DM / 128,  BS_TOTAL / 128), 256>>>(x, wq, pQ, BS_TOTAL, DM,  DM);
    sgemm_nt<<<dim3(KVW / 128, BS_TOTAL / 128), 256>>>(x, wk, pK, BS_TOTAL, KVW, DM);
    sgemm_nt<<<dim3(KVW / 128, BS_TOTAL / 128), 256>>>(x, wv, pV, BS_TOTAL, KVW, DM);

    // RoPE on Q and K
    rope_apply_kernel<<<(BS_TOTAL * NH  * 64 + 255) / 256, 256>>>(pQ, NH);
    rope_apply_kernel<<<(BS_TOTAL * NKV * 64 + 255) / 256, 256>>>(pK, NKV);

    // causal GQA flash attention -> g_O laid out [BS, H*D]
    attn_kernel<<<dim3(SEQ / 32, NH, B2), 128>>>();

    // output projection: out = O @ wo^T
    sgemm_nt<<<dim3(DM / 128, BS_TOTAL / 128), 256>>>(pO, wo, out, BS_TOTAL, DM, DM);
}

// round 2
// speedup vs baseline: 1.1497x; 1.1497x over previous
#include <cuda_runtime.h>
#include <math.h>
#include <stdint.h>

// Problem constants
#define B2      2
#define SEQ     2048
#define DM      2048
#define NH      16
#define NKV     4
#define HD      128
#define BS_TOTAL (B2*SEQ)        // 4096
#define KVW     (NKV*HD)         // 512

// ---------------- scratch (allocation-free: __device__ globals) ----------------
__device__ float g_Q[(size_t)BS_TOTAL * DM];    // 32 MB
__device__ float g_K[(size_t)BS_TOTAL * KVW];   // 8 MB
__device__ float g_V[(size_t)BS_TOTAL * KVW];   // 8 MB
__device__ float g_O[(size_t)BS_TOTAL * DM];    // 32 MB
__device__ float g_cos[SEQ * 64];
__device__ float g_sin[SEQ * 64];

// ---------------- RoPE table (fp64 phase -> fp32 cos/sin) ----------------
__global__ void rope_table_kernel() {
    int idx = blockIdx.x * blockDim.x + threadIdx.x;
    if (idx >= SEQ * 64) return;
    int s = idx >> 6, j = idx & 63;
    double inv = 1.0 / pow(10000.0, (double)(2 * j) / 128.0);
    double ph = (double)s * inv;
    g_cos[idx] = (float)cos(ph);
    g_sin[idx] = (float)sin(ph);
}

// ---------------- RoPE apply (in-place, NeoX pairing d <-> d+64) ----------------
__global__ void rope_apply_kernel(float* __restrict__ buf, int nheads) {
    int idx = blockIdx.x * blockDim.x + threadIdx.x;
    int total = BS_TOTAL * nheads * 64;
    if (idx >= total) return;
    int j = idx & 63;
    int tmp = idx >> 6;
    int h = tmp % nheads;
    int rowi = tmp / nheads;
    int s = rowi & (SEQ - 1);
    float c = g_cos[s * 64 + j];
    float sn = g_sin[s * 64 + j];
    size_t base = (size_t)rowi * (nheads * HD) + h * HD + j;
    float x1 = buf[base];
    float x2 = buf[base + 64];
    buf[base]      = x1 * c - x2 * sn;
    buf[base + 64] = x2 * c + x1 * sn;
}

// ---------------- TF32 tensor-core NT GEMM ----------------
// C[M,N] = A[M,K] * B[N,K]^T. Tile 128x128x32, 256 threads (8 warps, 2x4),
// warp tile 64x32 via mma.sync.m16n8k8.tf32. K-permuted smem layout:
// pos(k) = (k&~7) | ((k&3)<<1) | ((k>>2)&1)  => fragment pair (c, c+4) is
// adjacent, loaded as one ld.shared.v2. Row stride 40 (mod32=8) keeps the
// 8-row fragment loads conflict-free.

__device__ __forceinline__ uint32_t f2tf32(float v) {
    uint32_t r;
    asm("cvt.rna.tf32.f32 %0, %1;" : "=r"(r) : "f"(v));
    return r;
}

__device__ __forceinline__ void mma_tf32(float* acc, const uint32_t* a, const uint32_t* b) {
    asm volatile(
        "mma.sync.aligned.m16n8k8.row.col.f32.tf32.tf32.f32 "
        "{%0,%1,%2,%3}, {%4,%5,%6,%7}, {%8,%9}, {%0,%1,%2,%3};"
        : "+f"(acc[0]), "+f"(acc[1]), "+f"(acc[2]), "+f"(acc[3])
        : "r"(a[0]), "r"(a[1]), "r"(a[2]), "r"(a[3]), "r"(b[0]), "r"(b[1]));
}

#define SMS 40  // smem row stride (floats)

__global__ __launch_bounds__(256) void tgemm_nt(
    const float* __restrict__ A, const float* __restrict__ B,
    float* __restrict__ C, int M, int N, int K)
{
    __shared__ uint32_t As[128][SMS];
    __shared__ uint32_t Bs[128][SMS];

    const int t  = threadIdx.x;
    const int m0 = blockIdx.y * 128;
    const int n0 = blockIdx.x * 128;
    const int wid = t >> 5, lane = t & 31;
    const int warp_m = wid & 1;        // 2 warps along M (64 each)
    const int warp_n = wid >> 1;       // 4 warps along N (32 each)
    const int grp = lane >> 2, qid = lane & 3;

    // global load roles: row = t>>1 (128 rows), k-half = t&1 (16 floats)
    const int lrow = t >> 1, kh = t & 1;
    const float* Ag = A + (size_t)(m0 + lrow) * K + kh * 16;
    const float* Bg = B + (size_t)(n0 + lrow) * K + kh * 16;

    float acc[4][4][4];
    #pragma unroll
    for (int i = 0; i < 4; i++)
        #pragma unroll
        for (int j = 0; j < 4; j++)
            #pragma unroll
            for (int c = 0; c < 4; c++) acc[i][j][c] = 0.f;

    float4 ra[4], rb[4];
    #pragma unroll
    for (int c = 0; c < 4; c++) {
        ra[c] = *(const float4*)(Ag + c * 4);
        rb[c] = *(const float4*)(Bg + c * 4);
    }

    auto store_sm = [&]() {
        #pragma unroll
        for (int c = 0; c < 4; c++) {
            #pragma unroll
            for (int e = 0; e < 4; e++) {
                int k = kh * 16 + c * 4 + e;
                int pos = (k & ~7) | ((k & 3) << 1) | ((k >> 2) & 1);
                As[lrow][pos] = f2tf32(((const float*)&ra[c])[e]);
                Bs[lrow][pos] = f2tf32(((const float*)&rb[c])[e]);
            }
        }
    };
    store_sm();
    __syncthreads();

    for (int kb = 0; kb < K; kb += 32) {
        const bool has_next = (kb + 32) < K;
        if (has_next) {
            #pragma unroll
            for (int c = 0; c < 4; c++) {
                ra[c] = *(const float4*)(Ag + kb + 32 + c * 4);
                rb[c] = *(const float4*)(Bg + kb + 32 + c * 4);
            }
        }
        #pragma unroll
        for (int ks = 0; ks < 4; ks++) {
            uint32_t af[4][4];
            #pragma unroll
            for (int mf = 0; mf < 4; mf++) {
                uint2 lo = *(const uint2*)&As[warp_m * 64 + mf * 16 + grp][ks * 8 + 2 * qid];
                uint2 hi = *(const uint2*)&As[warp_m * 64 + mf * 16 + 8 + grp][ks * 8 + 2 * qid];
                af[mf][0] = lo.x; af[mf][1] = hi.x; af[mf][2] = lo.y; af[mf][3] = hi.y;
            }
            uint32_t bf[4][2];
            #pragma unroll
            for (int nf = 0; nf < 4; nf++) {
                uint2 bv = *(const uint2*)&Bs[warp_n * 32 + nf * 8 + grp][ks * 8 + 2 * qid];
                bf[nf][0] = bv.x; bf[nf][1] = bv.y;
            }
            #pragma unroll
            for (int mf = 0; mf < 4; mf++)
                #pragma unroll
                for (int nf = 0; nf < 4; nf++)
                    mma_tf32(acc[mf][nf], af[mf], bf[nf]);
        }
        if (has_next) {
            __syncthreads();
            store_sm();
            __syncthreads();
        }
    }

    // epilogue: c0,c1 at (r, 2q), c2,c3 at (r+8, 2q)
    #pragma unroll
    for (int mf = 0; mf < 4; mf++) {
        int r = m0 + warp_m * 64 + mf * 16 + grp;
        #pragma unroll
        for (int nf = 0; nf < 4; nf++) {
            int col = n0 + warp_n * 32 + nf * 8 + 2 * qid;
            float* Cp0 = C + (size_t)r * N + col;
            float* Cp1 = C + (size_t)(r + 8) * N + col;
            *(float2*)Cp0 = make_float2(acc[mf][nf][0], acc[mf][nf][1]);
            *(float2*)Cp1 = make_float2(acc[mf][nf][2], acc[mf][nf][3]);
        }
    }
}

// ---------------- Flash attention (causal, GQA), fp32 ----------------
__global__ __launch_bounds__(128) void attn_kernel() {
    __shared__ float k_s[32][144];
    __shared__ float v_s[32][144];
    const int qt = blockIdx.x, h = blockIdx.y, b = blockIdx.z;
    const int t = threadIdx.x;
    const int i = t >> 2, quarter = t & 3;
    const int q0 = qt * 32;
    const int kvh = h >> 2;
    const int sq = q0 + i;
    const size_t qrow = (size_t)(b * SEQ + sq);
    const float scale = 0.08838834764831845f;  // 1/sqrt(128)

    float q[32];
    {
        const float* qp = g_Q + qrow * DM + h * HD + quarter * 32;
        #pragma unroll
        for (int c = 0; c < 8; c++) {
            float4 v = *(const float4*)(qp + c * 4);
            q[c*4+0] = v.x * scale; q[c*4+1] = v.y * scale;
            q[c*4+2] = v.z * scale; q[c*4+3] = v.w * scale;
        }
    }
    float o[32];
    #pragma unroll
    for (int dd = 0; dd < 32; dd++) o[dd] = 0.f;
    float m = -INFINITY, l = 0.f;

    const int jrow = t >> 2, qq = t & 3;
    const int ntiles = qt + 1;

    for (int kt = 0; kt < ntiles; kt++) {
        const int k0 = kt * 32;
        __syncthreads();
        {
            const float* kp = g_K + (size_t)(b * SEQ + k0 + jrow) * KVW + kvh * HD + qq * 32;
            const float* vp = g_V + (size_t)(b * SEQ + k0 + jrow) * KVW + kvh * HD + qq * 32;
            #pragma unroll
            for (int c = 0; c < 8; c++) {
                float4 kv = *(const float4*)(kp + c * 4);
                float4 vv = *(const float4*)(vp + c * 4);
                *(float4*)&k_s[jrow][qq * 36 + c * 4] = kv;
                *(float4*)&v_s[jrow][qq * 36 + c * 4] = vv;
            }
        }
        __syncthreads();

        float s[32];
        #pragma unroll
        for (int j = 0; j < 32; j++) {
            const float* kr = &k_s[j][quarter * 36];
            float acc = 0.f;
            #pragma unroll
            for (int dd = 0; dd < 32; dd += 4) {
                float4 kv = *(const float4*)(kr + dd);
                acc += q[dd] * kv.x + q[dd+1] * kv.y + q[dd+2] * kv.z + q[dd+3] * kv.w;
            }
            acc += __shfl_xor_sync(0xffffffffu, acc, 1);
            acc += __shfl_xor_sync(0xffffffffu, acc, 2);
            s[j] = acc;
        }
        if (kt == qt) {
            #pragma unroll
            for (int j = 0; j < 32; j++)
                if (k0 + j > sq) s[j] = -INFINITY;
        }

        float mt = s[0];
        #pragma unroll
        for (int j = 1; j < 32; j++) mt = fmaxf(mt, s[j]);
        float mn = fmaxf(m, mt);
        float corr = __expf(fmaxf(m - mn, -80.f));
        l *= corr;
        #pragma unroll
        for (int dd = 0; dd < 32; dd++) o[dd] *= corr;
        float ls = 0.f;
        #pragma unroll
        for (int j = 0; j < 32; j++) {
            float p = __expf(s[j] - mn);
            s[j] = p;
            ls += p;
        }
        l += ls;
        m = mn;

        #pragma unroll
        for (int j = 0; j < 32; j++) {
            const float pj = s[j];
            const float* vr = &v_s[j][quarter * 36];
            #pragma unroll
            for (int dd = 0; dd < 32; dd += 4) {
                float4 vv = *(const float4*)(vr + dd);
                o[dd]   += pj * vv.x; o[dd+1] += pj * vv.y;
                o[dd+2] += pj * vv.z; o[dd+3] += pj * vv.w;
            }
        }
    }

    const float invl = 1.f / l;
    float* op = g_O + qrow * DM + h * HD + quarter * 32;
    #pragma unroll
    for (int c = 0; c < 8; c++) {
        float4 v = make_float4(o[c*4]*invl, o[c*4+1]*invl, o[c*4+2]*invl, o[c*4+3]*invl);
        *(float4*)(op + c * 4) = v;
    }
}

// ---------------- launch ----------------
extern "C" void kernel_launch(void* const* d_in, const int* in_sizes, int n_in,
                              void* d_out, int out_size) {
    const float* x  = (const float*)d_in[0];
    const float* wq = (const float*)d_in[1];
    const float* wk = (const float*)d_in[2];
    const float* wv = (const float*)d_in[3];
    const float* wo = (const float*)d_in[4];
    float* out = (float*)d_out;

    float *pQ, *pK, *pV, *pO;
    cudaGetSymbolAddress((void**)&pQ, g_Q);
    cudaGetSymbolAddress((void**)&pK, g_K);
    cudaGetSymbolAddress((void**)&pV, g_V);
    cudaGetSymbolAddress((void**)&pO, g_O);

    rope_table_kernel<<<(SEQ * 64 + 255) / 256, 256>>>();

    // QKV projections: C = X @ W^T (TF32 tensor cores)
    tgemm_nt<<<dim3(DM / 128,  BS_TOTAL / 128), 256>>>(x, wq, pQ, BS_TOTAL, DM,  DM);
    tgemm_nt<<<dim3(KVW / 128, BS_TOTAL / 128), 256>>>(x, wk, pK, BS_TOTAL, KVW, DM);
    tgemm_nt<<<dim3(KVW / 128, BS_TOTAL / 128), 256>>>(x, wv, pV, BS_TOTAL, KVW, DM);

    // RoPE on Q and K
    rope_apply_kernel<<<(BS_TOTAL * NH  * 64 + 255) / 256, 256>>>(pQ, NH);
    rope_apply_kernel<<<(BS_TOTAL * NKV * 64 + 255) / 256, 256>>>(pK, NKV);

    // causal GQA flash attention -> g_O laid out [BS, H*D]
    attn_kernel<<<dim3(SEQ / 32, NH, B2), 128>>>();

    // output projection: out = O @ wo^T (TF32 tensor cores)
    tgemm_nt<<<dim3(DM / 128, BS_TOTAL / 128), 256>>>(pO, wo, out, BS_TOTAL, DM, DM);
}

// round 3
// speedup vs baseline: 2.2088x; 1.9213x over previous
#include <cuda_runtime.h>
#include <math.h>
#include <stdint.h>

// Problem constants
#define B2      2
#define SEQ     2048
#define DM      2048
#define NH      16
#define NKV     4
#define HD      128
#define BS_TOTAL (B2*SEQ)        // 4096
#define KVW     (NKV*HD)         // 512

// ---------------- scratch ----------------
__device__ float g_Q[(size_t)BS_TOTAL * DM];
__device__ float g_K[(size_t)BS_TOTAL * KVW];
__device__ float g_V[(size_t)BS_TOTAL * KVW];
__device__ float g_O[(size_t)BS_TOTAL * DM];
__device__ float g_cos[SEQ * 64];
__device__ float g_sin[SEQ * 64];

// ---------------- RoPE ----------------
__global__ void rope_table_kernel() {
    int idx = blockIdx.x * blockDim.x + threadIdx.x;
    if (idx >= SEQ * 64) return;
    int s = idx >> 6, j = idx & 63;
    double inv = 1.0 / pow(10000.0, (double)(2 * j) / 128.0);
    double ph = (double)s * inv;
    g_cos[idx] = (float)cos(ph);
    g_sin[idx] = (float)sin(ph);
}

__global__ void rope_apply_kernel(float* __restrict__ buf, int nheads) {
    int idx = blockIdx.x * blockDim.x + threadIdx.x;
    int total = BS_TOTAL * nheads * 64;
    if (idx >= total) return;
    int j = idx & 63;
    int tmp = idx >> 6;
    int h = tmp % nheads;
    int rowi = tmp / nheads;
    int s = rowi & (SEQ - 1);
    float c = g_cos[s * 64 + j];
    float sn = g_sin[s * 64 + j];
    size_t base = (size_t)rowi * (nheads * HD) + h * HD + j;
    float x1 = buf[base];
    float x2 = buf[base + 64];
    buf[base]      = x1 * c - x2 * sn;
    buf[base + 64] = x2 * c + x1 * sn;
}

// ---------------- TF32 helpers ----------------
__device__ __forceinline__ uint32_t f2tf32(float v) {
    uint32_t r;
    asm("cvt.rna.tf32.f32 %0, %1;" : "=r"(r) : "f"(v));
    return r;
}
__device__ __forceinline__ void mma_tf32(float* acc, const uint32_t* a, const uint32_t* b) {
    asm volatile(
        "mma.sync.aligned.m16n8k8.row.col.f32.tf32.tf32.f32 "
        "{%0,%1,%2,%3}, {%4,%5,%6,%7}, {%8,%9}, {%0,%1,%2,%3};"
        : "+f"(acc[0]), "+f"(acc[1]), "+f"(acc[2]), "+f"(acc[3])
        : "r"(a[0]), "r"(a[1]), "r"(a[2]), "r"(a[3]), "r"(b[0]), "r"(b[1]));
}

// ---------------- TF32 tensor-core NT GEMM (128x128x32) ----------------
#define SMS 40

__global__ __launch_bounds__(256, 2) void tgemm_nt(
    const float* __restrict__ A, const float* __restrict__ B,
    float* __restrict__ C, int M, int N, int K)
{
    __shared__ uint32_t As[128][SMS];
    __shared__ uint32_t Bs[128][SMS];

    const int t  = threadIdx.x;
    const int m0 = blockIdx.y * 128;
    const int n0 = blockIdx.x * 128;
    const int wid = t >> 5, lane = t & 31;
    const int warp_m = wid & 1;
    const int warp_n = wid >> 1;
    const int grp = lane >> 2, qid = lane & 3;
    const int lrow = t >> 1, kh = t & 1;

    const float* Ag = A + (size_t)(m0 + lrow) * K + kh * 16;
    const float* Bg = B + (size_t)(n0 + lrow) * K + kh * 16;

    float acc[4][4][4];
    #pragma unroll
    for (int i = 0; i < 4; i++)
        #pragma unroll
        for (int j = 0; j < 4; j++)
            #pragma unroll
            for (int c = 0; c < 4; c++) acc[i][j][c] = 0.f;

    float4 ra[4], rb[4];
    #pragma unroll
    for (int c = 0; c < 4; c++) {
        ra[c] = *(const float4*)(Ag + c * 4);
        rb[c] = *(const float4*)(Bg + c * 4);
    }

    auto store_sm = [&]() {
        #pragma unroll
        for (int c = 0; c < 4; c++) {
            #pragma unroll
            for (int e = 0; e < 4; e++) {
                int k = kh * 16 + c * 4 + e;
                int pos = (k & ~7) | ((k & 3) << 1) | ((k >> 2) & 1);
                As[lrow][pos] = f2tf32(((const float*)&ra[c])[e]);
                Bs[lrow][pos] = f2tf32(((const float*)&rb[c])[e]);
            }
        }
    };
    store_sm();
    __syncthreads();

    for (int kb = 0; kb < K; kb += 32) {
        const bool has_next = (kb + 32) < K;
        if (has_next) {
            #pragma unroll
            for (int c = 0; c < 4; c++) {
                ra[c] = *(const float4*)(Ag + kb + 32 + c * 4);
                rb[c] = *(const float4*)(Bg + kb + 32 + c * 4);
            }
        }
        #pragma unroll
        for (int ks = 0; ks < 4; ks++) {
            uint32_t af[4][4];
            #pragma unroll
            for (int mf = 0; mf < 4; mf++) {
                uint2 lo = *(const uint2*)&As[warp_m * 64 + mf * 16 + grp][ks * 8 + 2 * qid];
                uint2 hi = *(const uint2*)&As[warp_m * 64 + mf * 16 + 8 + grp][ks * 8 + 2 * qid];
                af[mf][0] = lo.x; af[mf][1] = hi.x; af[mf][2] = lo.y; af[mf][3] = hi.y;
            }
            uint32_t bf[4][2];
            #pragma unroll
            for (int nf = 0; nf < 4; nf++) {
                uint2 bv = *(const uint2*)&Bs[warp_n * 32 + nf * 8 + grp][ks * 8 + 2 * qid];
                bf[nf][0] = bv.x; bf[nf][1] = bv.y;
            }
            #pragma unroll
            for (int mf = 0; mf < 4; mf++)
                #pragma unroll
                for (int nf = 0; nf < 4; nf++)
                    mma_tf32(acc[mf][nf], af[mf], bf[nf]);
        }
        if (has_next) {
            __syncthreads();
            store_sm();
            __syncthreads();
        }
    }

    #pragma unroll
    for (int mf = 0; mf < 4; mf++) {
        int r = m0 + warp_m * 64 + mf * 16 + grp;
        #pragma unroll
        for (int nf = 0; nf < 4; nf++) {
            int col = n0 + warp_n * 32 + nf * 8 + 2 * qid;
            float* Cp0 = C + (size_t)r * N + col;
            float* Cp1 = C + (size_t)(r + 8) * N + col;
            *(float2*)Cp0 = make_float2(acc[mf][nf][0], acc[mf][nf][1]);
            *(float2*)Cp1 = make_float2(acc[mf][nf][2], acc[mf][nf][3]);
        }
    }
}

// ---------------- fused K+V projection (two B, two C) ----------------
__global__ __launch_bounds__(256, 2) void tgemm_nt_kv(
    const float* __restrict__ A,
    const float* __restrict__ Bk, const float* __restrict__ Bv,
    float* __restrict__ Ck, float* __restrict__ Cv, int M, int K)
{
    __shared__ uint32_t As[128][SMS];
    __shared__ uint32_t Bs[128][SMS];

    const int t  = threadIdx.x;
    const int m0 = blockIdx.y * 128;
    const bool isv = blockIdx.x >= 4;
    const int n0 = (isv ? (blockIdx.x - 4) : blockIdx.x) * 128;
    const float* B = isv ? Bv : Bk;
    float* C = isv ? Cv : Ck;
    const int N = KVW;

    const int wid = t >> 5, lane = t & 31;
    const int warp_m = wid & 1;
    const int warp_n = wid >> 1;
    const int grp = lane >> 2, qid = lane & 3;
    const int lrow = t >> 1, kh = t & 1;

    const float* Ag = A + (size_t)(m0 + lrow) * K + kh * 16;
    const float* Bg = B + (size_t)(n0 + lrow) * K + kh * 16;

    float acc[4][4][4];
    #pragma unroll
    for (int i = 0; i < 4; i++)
        #pragma unroll
        for (int j = 0; j < 4; j++)
            #pragma unroll
            for (int c = 0; c < 4; c++) acc[i][j][c] = 0.f;

    float4 ra[4], rb[4];
    #pragma unroll
    for (int c = 0; c < 4; c++) {
        ra[c] = *(const float4*)(Ag + c * 4);
        rb[c] = *(const float4*)(Bg + c * 4);
    }
    auto store_sm = [&]() {
        #pragma unroll
        for (int c = 0; c < 4; c++) {
            #pragma unroll
            for (int e = 0; e < 4; e++) {
                int k = kh * 16 + c * 4 + e;
                int pos = (k & ~7) | ((k & 3) << 1) | ((k >> 2) & 1);
                As[lrow][pos] = f2tf32(((const float*)&ra[c])[e]);
                Bs[lrow][pos] = f2tf32(((const float*)&rb[c])[e]);
            }
        }
    };
    store_sm();
    __syncthreads();

    for (int kb = 0; kb < K; kb += 32) {
        const bool has_next = (kb + 32) < K;
        if (has_next) {
            #pragma unroll
            for (int c = 0; c < 4; c++) {
                ra[c] = *(const float4*)(Ag + kb + 32 + c * 4);
                rb[c] = *(const float4*)(Bg + kb + 32 + c * 4);
            }
        }
        #pragma unroll
        for (int ks = 0; ks < 4; ks++) {
            uint32_t af[4][4];
            #pragma unroll
            for (int mf = 0; mf < 4; mf++) {
                uint2 lo = *(const uint2*)&As[warp_m * 64 + mf * 16 + grp][ks * 8 + 2 * qid];
                uint2 hi = *(const uint2*)&As[warp_m * 64 + mf * 16 + 8 + grp][ks * 8 + 2 * qid];
                af[mf][0] = lo.x; af[mf][1] = hi.x; af[mf][2] = lo.y; af[mf][3] = hi.y;
            }
            uint32_t bf[4][2];
            #pragma unroll
            for (int nf = 0; nf < 4; nf++) {
                uint2 bv = *(const uint2*)&Bs[warp_n * 32 + nf * 8 + grp][ks * 8 + 2 * qid];
                bf[nf][0] = bv.x; bf[nf][1] = bv.y;
            }
            #pragma unroll
            for (int mf = 0; mf < 4; mf++)
                #pragma unroll
                for (int nf = 0; nf < 4; nf++)
                    mma_tf32(acc[mf][nf], af[mf], bf[nf]);
        }
        if (has_next) {
            __syncthreads();
            store_sm();
            __syncthreads();
        }
    }

    #pragma unroll
    for (int mf = 0; mf < 4; mf++) {
        int r = m0 + warp_m * 64 + mf * 16 + grp;
        #pragma unroll
        for (int nf = 0; nf < 4; nf++) {
            int col = n0 + warp_n * 32 + nf * 8 + 2 * qid;
            float* Cp0 = C + (size_t)r * N + col;
            float* Cp1 = C + (size_t)(r + 8) * N + col;
            *(float2*)Cp0 = make_float2(acc[mf][nf][0], acc[mf][nf][1]);
            *(float2*)Cp1 = make_float2(acc[mf][nf][2], acc[mf][nf][3]);
        }
    }
}

// ---------------- TF32 tensor-core flash attention ----------------
// 64 q-rows x 64 keys per CTA, 4 warps (16 q-rows each), d=128.
// S = Q*K^T via m16n8k8; softmax in accumulator registers; O += P*V with the
// sigma key-permutation trick (S accumulator layout == A fragment layout for
// P, V rows stored permuted). No shuffles, no smem roundtrip for P.
#define KSTR 132   // stride mod 32 = 4: (grp row, qid col) frag loads conflict-free
#define VSTR 136   // stride mod 32 = 8: (qid row, grp col) frag loads conflict-free
#define ATT_SMEM ((64*KSTR + 64*VSTR) * 4)

__global__ __launch_bounds__(128) void attn_tc_kernel() {
    extern __shared__ uint32_t sm[];
    uint32_t* sQK = sm;              // Q, then K (reused)  [64][KSTR]
    uint32_t* sV  = sm + 64 * KSTR;  // V (tf32, row-permuted) [64][VSTR]

    const int qt = blockIdx.x, h = blockIdx.y, b = blockIdx.z;
    const int t = threadIdx.x;
    const int w = t >> 5, lane = t & 31;
    const int grp = lane >> 2, qid = lane & 3;
    const int q0 = qt * 64;
    const int kvh = h >> 2;
    const float scale = 0.08838834764831845f;

    const int lrow = t >> 1, half = t & 1;   // load roles: 64 rows x 2 col-halves

    // ---- load Q tile (scaled, tf32, d-permuted) ----
    {
        const float* qp = g_Q + (size_t)(b * SEQ + q0 + lrow) * DM + h * HD + half * 64;
        #pragma unroll
        for (int c = 0; c < 16; c++) {
            float4 v = *(const float4*)(qp + c * 4);
            #pragma unroll
            for (int e = 0; e < 4; e++) {
                int d = half * 64 + c * 4 + e;
                int pos = (d & ~7) | ((d & 3) << 1) | ((d >> 2) & 1);
                sQK[lrow * KSTR + pos] = f2tf32(((const float*)&v)[e] * scale);
            }
        }
    }
    __syncthreads();

    // ---- extract Q fragments ----
    uint32_t aQ[16][4];
    #pragma unroll
    for (int c = 0; c < 16; c++) {
        uint2 lo = *(const uint2*)&sQK[(w * 16 + grp) * KSTR + c * 8 + 2 * qid];
        uint2 hi = *(const uint2*)&sQK[(w * 16 + 8 + grp) * KSTR + c * 8 + 2 * qid];
        aQ[c][0] = lo.x; aQ[c][1] = hi.x; aQ[c][2] = lo.y; aQ[c][3] = hi.y;
    }

    float sO[16][4];
    #pragma unroll
    for (int nt = 0; nt < 16; nt++)
        #pragma unroll
        for (int c = 0; c < 4; c++) sO[nt][c] = 0.f;
    float m0r = -INFINITY, m1r = -INFINITY, l0 = 0.f, l1 = 0.f;

    const int rq0 = q0 + w * 16 + grp;
    const int rq1 = rq0 + 8;

    for (int kt = 0; kt <= qt; kt++) {
        const int k0 = kt * 64;
        __syncthreads();
        // ---- load K (d-permuted) and V (row sigma-permuted) ----
        {
            const float* kp = g_K + (size_t)(b * SEQ + k0 + lrow) * KVW + kvh * HD + half * 64;
            const float* vp = g_V + (size_t)(b * SEQ + k0 + lrow) * KVW + kvh * HD + half * 64;
            int vrow = (lrow & ~7) | ((lrow & 1) << 2) | ((lrow >> 1) & 3);
            #pragma unroll
            for (int c = 0; c < 16; c++) {
                float4 kv = *(const float4*)(kp + c * 4);
                float4 vv = *(const float4*)(vp + c * 4);
                #pragma unroll
                for (int e = 0; e < 4; e++) {
                    int d = half * 64 + c * 4 + e;
                    int pos = (d & ~7) | ((d & 3) << 1) | ((d >> 2) & 1);
                    sQK[lrow * KSTR + pos] = f2tf32(((const float*)&kv)[e]);
                    sV[vrow * VSTR + d]    = f2tf32(((const float*)&vv)[e]);
                }
            }
        }
        __syncthreads();

        // ---- S = Q * K^T : 8 n-tiles of 8 keys ----
        float sS[8][4];
        #pragma unroll
        for (int nt = 0; nt < 8; nt++)
            #pragma unroll
            for (int c = 0; c < 4; c++) sS[nt][c] = 0.f;
        #pragma unroll
        for (int c = 0; c < 16; c++) {
            #pragma unroll
            for (int nt = 0; nt < 8; nt++) {
                uint2 bv = *(const uint2*)&sQK[(nt * 8 + grp) * KSTR + c * 8 + 2 * qid];
                uint32_t bf[2] = {bv.x, bv.y};
                mma_tf32(sS[nt], aQ[c], bf);
            }
        }

        // ---- causal mask (diagonal tile) ----
        if (kt == qt) {
            #pragma unroll
            for (int nt = 0; nt < 8; nt++) {
                int cj = k0 + nt * 8 + 2 * qid;
                if (cj > rq0)     sS[nt][0] = -INFINITY;
                if (cj + 1 > rq0) sS[nt][1] = -INFINITY;
                if (cj > rq1)     sS[nt][2] = -INFINITY;
                if (cj + 1 > rq1) sS[nt][3] = -INFINITY;
            }
        }

        // ---- online softmax ----
        float mx0 = sS[0][0], mx1 = sS[0][2];
        #pragma unroll
        for (int nt = 0; nt < 8; nt++) {
            mx0 = fmaxf(mx0, fmaxf(sS[nt][0], sS[nt][1]));
            mx1 = fmaxf(mx1, fmaxf(sS[nt][2], sS[nt][3]));
        }
        mx0 = fmaxf(mx0, __shfl_xor_sync(0xffffffffu, mx0, 1));
        mx0 = fmaxf(mx0, __shfl_xor_sync(0xffffffffu, mx0, 2));
        mx1 = fmaxf(mx1, __shfl_xor_sync(0xffffffffu, mx1, 1));
        mx1 = fmaxf(mx1, __shfl_xor_sync(0xffffffffu, mx1, 2));

        float mn0 = fmaxf(m0r, mx0), mn1 = fmaxf(m1r, mx1);
        float corr0 = __expf(fmaxf(m0r - mn0, -80.f));
        float corr1 = __expf(fmaxf(m1r - mn1, -80.f));
        m0r = mn0; m1r = mn1;

        float s0 = 0.f, s1 = 0.f;
        #pragma unroll
        for (int nt = 0; nt < 8; nt++) {
            sS[nt][0] = __expf(sS[nt][0] - mn0);
            sS[nt][1] = __expf(sS[nt][1] - mn0);
            sS[nt][2] = __expf(sS[nt][2] - mn1);
            sS[nt][3] = __expf(sS[nt][3] - mn1);
            s0 += sS[nt][0] + sS[nt][1];
            s1 += sS[nt][2] + sS[nt][3];
        }
        s0 += __shfl_xor_sync(0xffffffffu, s0, 1);
        s0 += __shfl_xor_sync(0xffffffffu, s0, 2);
        s1 += __shfl_xor_sync(0xffffffffu, s1, 1);
        s1 += __shfl_xor_sync(0xffffffffu, s1, 2);
        l0 = l0 * corr0 + s0;
        l1 = l1 * corr1 + s1;

        #pragma unroll
        for (int nt = 0; nt < 16; nt++) {
            sO[nt][0] *= corr0; sO[nt][1] *= corr0;
            sO[nt][2] *= corr1; sO[nt][3] *= corr1;
        }

        // ---- O += P * V ----
        #pragma unroll
        for (int kk = 0; kk < 8; kk++) {
            uint32_t aP[4];
            aP[0] = f2tf32(sS[kk][0]);
            aP[1] = f2tf32(sS[kk][2]);
            aP[2] = f2tf32(sS[kk][1]);
            aP[3] = f2tf32(sS[kk][3]);
            #pragma unroll
            for (int nt = 0; nt < 16; nt++) {
                uint32_t bf[2];
                bf[0] = sV[(kk * 8 + qid) * VSTR + nt * 8 + grp];
                bf[1] = sV[(kk * 8 + qid + 4) * VSTR + nt * 8 + grp];
                mma_tf32(sO[nt], aP, bf);
            }
        }
    }

    // ---- epilogue ----
    const float invl0 = 1.f / l0, invl1 = 1.f / l1;
    float* op0 = g_O + (size_t)(b * SEQ + rq0) * DM + h * HD;
    float* op1 = g_O + (size_t)(b * SEQ + rq1) * DM + h * HD;
    #pragma unroll
    for (int nt = 0; nt < 16; nt++) {
        *(float2*)(op0 + nt * 8 + 2 * qid) = make_float2(sO[nt][0] * invl0, sO[nt][1] * invl0);
        *(float2*)(op1 + nt * 8 + 2 * qid) = make_float2(sO[nt][2] * invl1, sO[nt][3] * invl1);
    }
}

// ---------------- launch ----------------
extern "C" void kernel_launch(void* const* d_in, const int* in_sizes, int n_in,
                              void* d_out, int out_size) {
    const float* x  = (const float*)d_in[0];
    const float* wq = (const float*)d_in[1];
    const float* wk = (const float*)d_in[2];
    const float* wv = (const float*)d_in[3];
    const float* wo = (const float*)d_in[4];
    float* out = (float*)d_out;

    float *pQ, *pK, *pV, *pO;
    cudaGetSymbolAddress((void**)&pQ, g_Q);
    cudaGetSymbolAddress((void**)&pK, g_K);
    cudaGetSymbolAddress((void**)&pV, g_V);
    cudaGetSymbolAddress((void**)&pO, g_O);

    static bool attr_done = false;
    if (!attr_done) {
        cudaFuncSetAttribute(attn_tc_kernel,
                             cudaFuncAttributeMaxDynamicSharedMemorySize, ATT_SMEM);
        attr_done = true;
    }

    rope_table_kernel<<<(SEQ * 64 + 255) / 256, 256>>>();

    // Q projection + fused K/V projection
    tgemm_nt<<<dim3(DM / 128, BS_TOTAL / 128), 256>>>(x, wq, pQ, BS_TOTAL, DM, DM);
    tgemm_nt_kv<<<dim3(8, BS_TOTAL / 128), 256>>>(x, wk, wv, pK, pV, BS_TOTAL, DM);

    // RoPE
    rope_apply_kernel<<<(BS_TOTAL * NH  * 64 + 255) / 256, 256>>>(pQ, NH);
    rope_apply_kernel<<<(BS_TOTAL * NKV * 64 + 255) / 256, 256>>>(pK, NKV);

    // tensor-core causal GQA flash attention
    attn_tc_kernel<<<dim3(SEQ / 64, NH, B2), 128, ATT_SMEM>>>();

    // output projection
    tgemm_nt<<<dim3(DM / 128, BS_TOTAL / 128), 256>>>(pO, wo, out, BS_TOTAL, DM, DM);
}

// round 6
// speedup vs baseline: 3.0408x; 1.3767x over previous
#include <cuda_runtime.h>
#include <math.h>
#include <stdint.h>

// Problem constants
#define B2      2
#define SEQ     2048
#define DM      2048
#define NH      16
#define NKV     4
#define HD      128
#define BS_TOTAL (B2*SEQ)        // 4096
#define KVW     (NKV*HD)         // 512

// ---------------- scratch ----------------
__device__ float g_Q[(size_t)BS_TOTAL * DM];
__device__ float g_K[(size_t)BS_TOTAL * KVW];
__device__ float g_V[(size_t)BS_TOTAL * KVW];
__device__ float g_O[(size_t)BS_TOTAL * DM];
__device__ float g_cos[SEQ * 64];
__device__ float g_sin[SEQ * 64];
// tf32-rounded, k-permuted operand copies
__device__ uint32_t g_xp [(size_t)BS_TOTAL * DM];
__device__ uint32_t g_wqp[(size_t)DM * DM];
__device__ uint32_t g_wkp[(size_t)KVW * DM];
__device__ uint32_t g_wvp[(size_t)KVW * DM];
__device__ uint32_t g_wop[(size_t)DM * DM];
__device__ uint32_t g_op [(size_t)BS_TOTAL * DM];

// ---------------- TF32 helpers ----------------
__device__ __forceinline__ uint32_t f2tf32(float v) {
    uint32_t r;
    asm("cvt.rna.tf32.f32 %0, %1;" : "=r"(r) : "f"(v));
    return r;
}
__device__ __forceinline__ void mma_tf32(float* acc, const uint32_t* a, const uint32_t* b) {
    asm volatile(
        "mma.sync.aligned.m16n8k8.row.col.f32.tf32.tf32.f32 "
        "{%0,%1,%2,%3}, {%4,%5,%6,%7}, {%8,%9}, {%0,%1,%2,%3};"
        : "+f"(acc[0]), "+f"(acc[1]), "+f"(acc[2]), "+f"(acc[3])
        : "r"(a[0]), "r"(a[1]), "r"(a[2]), "r"(a[3]), "r"(b[0]), "r"(b[1]));
}
__device__ __forceinline__ void cp16(uint32_t dst, const void* src) {
    asm volatile("cp.async.cg.shared.global [%0], [%1], 16;\n" :: "r"(dst), "l"(src));
}
#define CP_COMMIT() asm volatile("cp.async.commit_group;\n" ::: "memory")
#define CP_WAIT1()  asm volatile("cp.async.wait_group 1;\n" ::: "memory")

// ---------------- RoPE ----------------
__global__ void rope_table_kernel() {
    int idx = blockIdx.x * blockDim.x + threadIdx.x;
    if (idx >= SEQ * 64) return;
    int s = idx >> 6, j = idx & 63;
    double inv = 1.0 / pow(10000.0, (double)(2 * j) / 128.0);
    double ph = (double)s * inv;
    g_cos[idx] = (float)cos(ph);
    g_sin[idx] = (float)sin(ph);
}

// RoPE apply; writes tf32-rounded output (optionally pre-scaled) so downstream
// tensor-core consumers can use raw bits with no conversion.
__global__ void rope_apply_kernel(float* __restrict__ buf, int nheads, float mul) {
    int idx = blockIdx.x * blockDim.x + threadIdx.x;
    int total = BS_TOTAL * nheads * 64;
    if (idx >= total) return;
    int j = idx & 63;
    int tmp = idx >> 6;
    int h = tmp % nheads;
    int rowi = tmp / nheads;
    int s = rowi & (SEQ - 1);
    float c = g_cos[s * 64 + j];
    float sn = g_sin[s * 64 + j];
    size_t base = (size_t)rowi * (nheads * HD) + h * HD + j;
    float x1 = buf[base];
    float x2 = buf[base + 64];
    uint32_t* ub = (uint32_t*)buf;
    ub[base]      = f2tf32((x1 * c - x2 * sn) * mul);
    ub[base + 64] = f2tf32((x2 * c + x1 * sn) * mul);
}

// ---------------- prep: tf32-round + k-permute (inner dim 2048) ----------------
__global__ void prep_kernel(const float* __restrict__ src, uint32_t* __restrict__ dst, int total) {
    int idx = blockIdx.x * blockDim.x + threadIdx.x;
    if (idx >= total) return;
    int k = idx & (DM - 1);
    int pos = (k & ~7) | ((k & 3) << 1) | ((k >> 2) & 1);
    dst[(idx & ~(DM - 1)) | pos] = f2tf32(src[idx]);
}

// ---------------- cp.async pipelined TF32 GEMM ----------------
// C[M,N] = A[M,K]*B[N,K]^T, A/B pre-rounded+permuted. Tile 128x128, BK=16,
// 3-stage cp.async ring, 256 threads (8 warps 2x4), warp tile 64x32.
// smem row stride 24 words: half-warp phase banks {0-7},{24-31},{16-23},{8-15}
// -> exact 32-bank cover, conflict-free LDS.64 fragment loads.
#define PSTR 24
#define NSTAGE 3
#define GEMM_SMEM (NSTAGE * 2 * 128 * PSTR * 4)

__device__ __forceinline__ void gemm_core(
    const uint32_t* __restrict__ A, const uint32_t* __restrict__ B,
    float* __restrict__ C, int m0, int n0, int N, int K, int roundC,
    uint32_t* smem_u)
{
    const int t = threadIdx.x;
    const int wid = t >> 5, lane = t & 31;
    const int warp_m = wid & 1;
    const int warp_n = wid >> 1;
    const int grp = lane >> 2, qid = lane & 3;
    const int r = t >> 1;           // load row
    const int cb = (t & 1) * 2;     // chunk base (16B chunks)

    const uint32_t* Arow = A + (size_t)(m0 + r) * K;
    const uint32_t* Brow = B + (size_t)(n0 + r) * K;
    uint32_t sbase = (uint32_t)__cvta_generic_to_shared(smem_u);

    auto issue = [&](int slab, int slot) {
        uint32_t dA = sbase + (uint32_t)((slot * 128 + r) * PSTR) * 4;
        uint32_t dB = sbase + (uint32_t)(((NSTAGE + slot) * 128 + r) * PSTR) * 4;
        const uint32_t* gA = Arow + slab * 16;
        const uint32_t* gB = Brow + slab * 16;
        cp16(dA + (cb    ) * 16, gA + (cb    ) * 4);
        cp16(dA + (cb + 1) * 16, gA + (cb + 1) * 4);
        cp16(dB + (cb    ) * 16, gB + (cb    ) * 4);
        cp16(dB + (cb + 1) * 16, gB + (cb + 1) * 4);
    };

    float acc[4][4][4];
    #pragma unroll
    for (int i = 0; i < 4; i++)
        #pragma unroll
        for (int j = 0; j < 4; j++)
            #pragma unroll
            for (int c = 0; c < 4; c++) acc[i][j][c] = 0.f;

    const int nslab = K >> 4;
    // prologue: stages 0,1
    issue(0, 0); CP_COMMIT();
    if (nslab > 1) issue(1, 1);
    CP_COMMIT();

    int slot = 0;
    for (int i = 0; i < nslab; i++) {
        CP_WAIT1();          // slab i landed (slab i+1 may be in flight)
        __syncthreads();     // all readers of slot (i-1)%3 are done
        int wslot = slot + 2; if (wslot >= NSTAGE) wslot -= NSTAGE;
        if (i + 2 < nslab) issue(i + 2, wslot);
        CP_COMMIT();

        const uint32_t* pA = smem_u + (size_t)slot * 128 * PSTR;
        const uint32_t* pB = smem_u + (size_t)(NSTAGE + slot) * 128 * PSTR;
        #pragma unroll
        for (int ks = 0; ks < 2; ks++) {
            uint32_t af[4][4], bf[4][2];
            #pragma unroll
            for (int mf = 0; mf < 4; mf++) {
                uint2 lo = *(const uint2*)&pA[(warp_m * 64 + mf * 16 + grp) * PSTR + ks * 8 + 2 * qid];
                uint2 hi = *(const uint2*)&pA[(warp_m * 64 + mf * 16 + 8 + grp) * PSTR + ks * 8 + 2 * qid];
                af[mf][0] = lo.x; af[mf][1] = hi.x; af[mf][2] = lo.y; af[mf][3] = hi.y;
            }
            #pragma unroll
            for (int nf = 0; nf < 4; nf++) {
                uint2 bv = *(const uint2*)&pB[(warp_n * 32 + nf * 8 + grp) * PSTR + ks * 8 + 2 * qid];
                bf[nf][0] = bv.x; bf[nf][1] = bv.y;
            }
            #pragma unroll
            for (int mf = 0; mf < 4; mf++)
                #pragma unroll
                for (int nf = 0; nf < 4; nf++)
                    mma_tf32(acc[mf][nf], af[mf], bf[nf]);
        }
        slot++; if (slot >= NSTAGE) slot = 0;
    }

    if (roundC) {
        #pragma unroll
        for (int mf = 0; mf < 4; mf++)
            #pragma unroll
            for (int nf = 0; nf < 4; nf++)
                #pragma unroll
                for (int c = 0; c < 4; c++)
                    acc[mf][nf][c] = __uint_as_float(f2tf32(acc[mf][nf][c]));
    }

    #pragma unroll
    for (int mf = 0; mf < 4; mf++) {
        int rr = m0 + warp_m * 64 + mf * 16 + grp;
        #pragma unroll
        for (int nf = 0; nf < 4; nf++) {
            int col = n0 + warp_n * 32 + nf * 8 + 2 * qid;
            float* Cp0 = C + (size_t)rr * N + col;
            float* Cp1 = C + (size_t)(rr + 8) * N + col;
            *(float2*)Cp0 = make_float2(acc[mf][nf][0], acc[mf][nf][1]);
            *(float2*)Cp1 = make_float2(acc[mf][nf][2], acc[mf][nf][3]);
        }
    }
}

__global__ __launch_bounds__(256, 2) void tgemm_ca(
    const uint32_t* __restrict__ A, const uint32_t* __restrict__ B,
    float* __restrict__ C, int N, int K)
{
    extern __shared__ uint32_t smem_u[];
    gemm_core(A, B, C, blockIdx.y * 128, blockIdx.x * 128, N, K, 0, smem_u);
}

// fused K+V projection; V output tf32-rounded (attention consumes raw bits)
__global__ __launch_bounds__(256, 2) void tgemm_ca_kv(
    const uint32_t* __restrict__ A,
    const uint32_t* __restrict__ Bk, const uint32_t* __restrict__ Bv,
    float* __restrict__ Ck, float* __restrict__ Cv, int K)
{
    extern __shared__ uint32_t smem_u[];
    const bool isv = blockIdx.x >= 4;
    gemm_core(A, isv ? Bv : Bk, isv ? Cv : Ck,
              blockIdx.y * 128, (isv ? blockIdx.x - 4 : blockIdx.x) * 128,
              KVW, K, isv ? 1 : 0, smem_u);
}

// ---------------- TF32 tensor-core flash attention ----------------
// 64 q x 64 k per CTA, 4 warps. Inputs pre-rounded to tf32 (rope / kv-gemm
// epilogue), so tile staging is pure bit copies. P rounded inline.
#define KSTR 132
#define VSTR 136
#define ATT_SMEM ((64*KSTR + 64*VSTR) * 4)

__global__ __launch_bounds__(128) void attn_tc_kernel() {
    extern __shared__ uint32_t sm[];
    uint32_t* sQK = sm;
    uint32_t* sV  = sm + 64 * KSTR;

    const int qt = blockIdx.x, h = blockIdx.y, b = blockIdx.z;
    const int t = threadIdx.x;
    const int w = t >> 5, lane = t & 31;
    const int grp = lane >> 2, qid = lane & 3;
    const int q0 = qt * 64;
    const int kvh = h >> 2;
    const int lrow = t >> 1, half = t & 1;

    // ---- load Q tile (already tf32-rounded + scaled by rope) ----
    {
        const uint32_t* qp = (const uint32_t*)g_Q + (size_t)(b * SEQ + q0 + lrow) * DM + h * HD + half * 64;
        #pragma unroll
        for (int c = 0; c < 16; c++) {
            uint4 v = *(const uint4*)(qp + c * 4);
            #pragma unroll
            for (int e = 0; e < 4; e++) {
                int d = half * 64 + c * 4 + e;
                int pos = (d & ~7) | ((d & 3) << 1) | ((d >> 2) & 1);
                sQK[lrow * KSTR + pos] = ((const uint32_t*)&v)[e];
            }
        }
    }
    __syncthreads();

    uint32_t aQ[16][4];
    #pragma unroll
    for (int c = 0; c < 16; c++) {
        uint2 lo = *(const uint2*)&sQK[(w * 16 + grp) * KSTR + c * 8 + 2 * qid];
        uint2 hi = *(const uint2*)&sQK[(w * 16 + 8 + grp) * KSTR + c * 8 + 2 * qid];
        aQ[c][0] = lo.x; aQ[c][1] = hi.x; aQ[c][2] = lo.y; aQ[c][3] = hi.y;
    }

    float sO[16][4];
    #pragma unroll
    for (int nt = 0; nt < 16; nt++)
        #pragma unroll
        for (int c = 0; c < 4; c++) sO[nt][c] = 0.f;
    float m0r = -INFINITY, m1r = -INFINITY, l0 = 0.f, l1 = 0.f;

    const int rq0 = q0 + w * 16 + grp;
    const int rq1 = rq0 + 8;

    for (int kt = 0; kt <= qt; kt++) {
        const int k0 = kt * 64;
        __syncthreads();
        {
            const uint32_t* kp = (const uint32_t*)g_K + (size_t)(b * SEQ + k0 + lrow) * KVW + kvh * HD + half * 64;
            const uint32_t* vp = (const uint32_t*)g_V + (size_t)(b * SEQ + k0 + lrow) * KVW + kvh * HD + half * 64;
            int vrow = (lrow & ~7) | ((lrow & 1) << 2) | ((lrow >> 1) & 3);
            #pragma unroll
            for (int c = 0; c < 16; c++) {
                uint4 kv = *(const uint4*)(kp + c * 4);
                uint4 vv = *(const uint4*)(vp + c * 4);
                #pragma unroll
                for (int e = 0; e < 4; e++) {
                    int d = half * 64 + c * 4 + e;
                    int pos = (d & ~7) | ((d & 3) << 1) | ((d >> 2) & 1);
                    sQK[lrow * KSTR + pos] = ((const uint32_t*)&kv)[e];
                    sV[vrow * VSTR + d]    = ((const uint32_t*)&vv)[e];
                }
            }
        }
        __syncthreads();

        float sS[8][4];
        #pragma unroll
        for (int nt = 0; nt < 8; nt++)
            #pragma unroll
            for (int c = 0; c < 4; c++) sS[nt][c] = 0.f;
        #pragma unroll
        for (int c = 0; c < 16; c++) {
            #pragma unroll
            for (int nt = 0; nt < 8; nt++) {
                uint2 bv = *(const uint2*)&sQK[(nt * 8 + grp) * KSTR + c * 8 + 2 * qid];
                uint32_t bf[2] = {bv.x, bv.y};
                mma_tf32(sS[nt], aQ[c], bf);
            }
        }

        if (kt == qt) {
            #pragma unroll
            for (int nt = 0; nt < 8; nt++) {
                int cj = k0 + nt * 8 + 2 * qid;
                if (cj > rq0)     sS[nt][0] = -INFINITY;
                if (cj + 1 > rq0) sS[nt][1] = -INFINITY;
                if (cj > rq1)     sS[nt][2] = -INFINITY;
                if (cj + 1 > rq1) sS[nt][3] = -INFINITY;
            }
        }

        float mx0 = sS[0][0], mx1 = sS[0][2];
        #pragma unroll
        for (int nt = 0; nt < 8; nt++) {
            mx0 = fmaxf(mx0, fmaxf(sS[nt][0], sS[nt][1]));
            mx1 = fmaxf(mx1, fmaxf(sS[nt][2], sS[nt][3]));
        }
        mx0 = fmaxf(mx0, __shfl_xor_sync(0xffffffffu, mx0, 1));
        mx0 = fmaxf(mx0, __shfl_xor_sync(0xffffffffu, mx0, 2));
        mx1 = fmaxf(mx1, __shfl_xor_sync(0xffffffffu, mx1, 1));
        mx1 = fmaxf(mx1, __shfl_xor_sync(0xffffffffu, mx1, 2));

        float mn0 = fmaxf(m0r, mx0), mn1 = fmaxf(m1r, mx1);
        float corr0 = __expf(fmaxf(m0r - mn0, -80.f));
        float corr1 = __expf(fmaxf(m1r - mn1, -80.f));
        m0r = mn0; m1r = mn1;

        float s0 = 0.f, s1 = 0.f;
        #pragma unroll
        for (int nt = 0; nt < 8; nt++) {
            sS[nt][0] = __expf(sS[nt][0] - mn0);
            sS[nt][1] = __expf(sS[nt][1] - mn0);
            sS[nt][2] = __expf(sS[nt][2] - mn1);
            sS[nt][3] = __expf(sS[nt][3] - mn1);
            s0 += sS[nt][0] + sS[nt][1];
            s1 += sS[nt][2] + sS[nt][3];
        }
        s0 += __shfl_xor_sync(0xffffffffu, s0, 1);
        s0 += __shfl_xor_sync(0xffffffffu, s0, 2);
        s1 += __shfl_xor_sync(0xffffffffu, s1, 1);
        s1 += __shfl_xor_sync(0xffffffffu, s1, 2);
        l0 = l0 * corr0 + s0;
        l1 = l1 * corr1 + s1;

        #pragma unroll
        for (int nt = 0; nt < 16; nt++) {
            sO[nt][0] *= corr0; sO[nt][1] *= corr0;
            sO[nt][2] *= corr1; sO[nt][3] *= corr1;
        }

        #pragma unroll
        for (int kk = 0; kk < 8; kk++) {
            uint32_t aP[4];
            aP[0] = f2tf32(sS[kk][0]);
            aP[1] = f2tf32(sS[kk][2]);
            aP[2] = f2tf32(sS[kk][1]);
            aP[3] = f2tf32(sS[kk][3]);
            #pragma unroll
            for (int nt = 0; nt < 16; nt++) {
                uint32_t bf[2];
                bf[0] = sV[(kk * 8 + qid) * VSTR + nt * 8 + grp];
                bf[1] = sV[(kk * 8 + qid + 4) * VSTR + nt * 8 + grp];
                mma_tf32(sO[nt], aP, bf);
            }
        }
    }

    const float invl0 = 1.f / l0, invl1 = 1.f / l1;
    float* op0 = g_O + (size_t)(b * SEQ + rq0) * DM + h * HD;
    float* op1 = g_O + (size_t)(b * SEQ + rq1) * DM + h * HD;
    #pragma unroll
    for (int nt = 0; nt < 16; nt++) {
        *(float2*)(op0 + nt * 8 + 2 * qid) = make_float2(sO[nt][0] * invl0, sO[nt][1] * invl0);
        *(float2*)(op1 + nt * 8 + 2 * qid) = make_float2(sO[nt][2] * invl1, sO[nt][3] * invl1);
    }
}

// ---------------- launch ----------------
extern "C" void kernel_launch(void* const* d_in, const int* in_sizes, int n_in,
                              void* d_out, int out_size) {
    const float* x  = (const float*)d_in[0];
    const float* wq = (const float*)d_in[1];
    const float* wk = (const float*)d_in[2];
    const float* wv = (const float*)d_in[3];
    const float* wo = (const float*)d_in[4];
    float* out = (float*)d_out;

    float *pQ, *pK, *pV, *pO;
    uint32_t *pxp, *pwqp, *pwkp, *pwvp, *pwop, *pop;
    cudaGetSymbolAddress((void**)&pQ, g_Q);
    cudaGetSymbolAddress((void**)&pK, g_K);
    cudaGetSymbolAddress((void**)&pV, g_V);
    cudaGetSymbolAddress((void**)&pO, g_O);
    cudaGetSymbolAddress((void**)&pxp, g_xp);
    cudaGetSymbolAddress((void**)&pwqp, g_wqp);
    cudaGetSymbolAddress((void**)&pwkp, g_wkp);
    cudaGetSymbolAddress((void**)&pwvp, g_wvp);
    cudaGetSymbolAddress((void**)&pwop, g_wop);
    cudaGetSymbolAddress((void**)&pop, g_op);

    cudaFuncSetAttribute(attn_tc_kernel,
                         cudaFuncAttributeMaxDynamicSharedMemorySize, ATT_SMEM);
    cudaFuncSetAttribute(tgemm_ca,
                         cudaFuncAttributeMaxDynamicSharedMemorySize, GEMM_SMEM);
    cudaFuncSetAttribute(tgemm_ca_kv,
                         cudaFuncAttributeMaxDynamicSharedMemorySize, GEMM_SMEM);

    rope_table_kernel<<<(SEQ * 64 + 255) / 256, 256>>>();

    // prep: tf32-round + permute operands
    prep_kernel<<<(BS_TOTAL * DM + 255) / 256, 256>>>(x,  pxp,  BS_TOTAL * DM);
    prep_kernel<<<(DM * DM + 255) / 256, 256>>>(wq, pwqp, DM * DM);
    prep_kernel<<<(KVW * DM + 255) / 256, 256>>>(wk, pwkp, KVW * DM);
    prep_kernel<<<(KVW * DM + 255) / 256, 256>>>(wv, pwvp, KVW * DM);
    prep_kernel<<<(DM * DM + 255) / 256, 256>>>(wo, pwop, DM * DM);

    // projections
    tgemm_ca<<<dim3(DM / 128, BS_TOTAL / 128), 256, GEMM_SMEM>>>(pxp, pwqp, pQ, DM, DM);
    tgemm_ca_kv<<<dim3(8, BS_TOTAL / 128), 256, GEMM_SMEM>>>(pxp, pwkp, pwvp, pK, pV, DM);

    // RoPE (writes tf32-rounded; Q pre-scaled by 1/sqrt(d))
    rope_apply_kernel<<<(BS_TOTAL * NH  * 64 + 255) / 256, 256>>>(pQ, NH, 0.08838834764831845f);
    rope_apply_kernel<<<(BS_TOTAL * NKV * 64 + 255) / 256, 256>>>(pK, NKV, 1.0f);

    // attention
    attn_tc_kernel<<<dim3(SEQ / 64, NH, B2), 128, ATT_SMEM>>>();

    // output projection
    prep_kernel<<<(BS_TOTAL * DM + 255) / 256, 256>>>(pO, pop, BS_TOTAL * DM);
    tgemm_ca<<<dim3(DM / 128, BS_TOTAL / 128), 256, GEMM_SMEM>>>(pop, pwop, out, DM, DM);
}